// round 16
// baseline (speedup 1.0000x reference)
#include <cuda_runtime.h>
#include <cstdint>

#define N_NODES 100000
#define N_EDGES 640000
#define D 128

// ---------------- scratch (device globals: no runtime allocation allowed) ---
static __device__ int   g_is64;
static __device__ int   g_esrc[N_EDGES];
static __device__ int   g_edst[N_EDGES];
static __device__ int   g_cnt[N_NODES];
static __device__ int   g_head[N_NODES];
static __device__ int   g_off[N_NODES + 1];
static __device__ int   g_ssrc[N_EDGES];
static __device__ float g_agg[(size_t)N_NODES * D];   // 51.2 MB
static __device__ float g_h1[(size_t)N_NODES * D];    // 51.2 MB
static __device__ float g_wcat[256 * 128];            // [Wl;Wr] transposed: [k][j]

// ---------------- edge dtype detection + conversion --------------------------
// JAX without x64 silently downcasts int64->int32. Detect which layout the
// harness actually gave us: if the buffer is int64 (little-endian, values
// < 2^31), every odd 32-bit word of the first 256 elements is 0. For an
// int32 buffer those words are random node ids (P[all 256 == 0] ~ 0).
__global__ void detect_kernel(const int* __restrict__ raw) {
    if (threadIdx.x == 0) {
        int nonzero = 0;
        #pragma unroll 8
        for (int i = 0; i < 256; i++) nonzero |= raw[2 * i + 1];
        g_is64 = (nonzero == 0) ? 1 : 0;
    }
}

__global__ void convert_kernel(const int* __restrict__ raw) {
    int e = blockIdx.x * blockDim.x + threadIdx.x;
    if (e >= 2 * N_EDGES) return;
    int v = g_is64 ? raw[2 * e] : raw[e];
    // clamp defensively so a wrong guess can't OOB (correctness check would
    // still catch a wrong answer)
    v = min(max(v, 0), N_NODES - 1);
    if (e < N_EDGES) g_esrc[e] = v;
    else             g_edst[e - N_EDGES] = v;
}

// ---------------- preprocessing ---------------------------------------------
__global__ void zero_counts_kernel() {
    int i = blockIdx.x * blockDim.x + threadIdx.x;
    if (i < N_NODES) { g_cnt[i] = 0; g_head[i] = 0; }
}

__global__ void count_kernel() {
    int e = blockIdx.x * blockDim.x + threadIdx.x;
    if (e < N_EDGES) atomicAdd(&g_cnt[g_edst[e]], 1);
}

// single-block exclusive scan over g_cnt -> g_off (N+1 entries)
__global__ void scan_kernel() {
    __shared__ int s[1024];
    int t = threadIdx.x;
    int carry = 0;
    for (int base = 0; base < N_NODES; base += 1024) {
        int i = base + t;
        int v = (i < N_NODES) ? g_cnt[i] : 0;
        s[t] = v;
        __syncthreads();
        for (int off = 1; off < 1024; off <<= 1) {
            int add = (t >= off) ? s[t - off] : 0;
            __syncthreads();
            s[t] += add;
            __syncthreads();
        }
        if (i < N_NODES) g_off[i] = carry + s[t] - v;   // exclusive
        carry += s[1023];
        __syncthreads();
    }
    if (t == 0) g_off[N_NODES] = carry;
}

__global__ void fill_kernel() {
    int e = blockIdx.x * blockDim.x + threadIdx.x;
    if (e < N_EDGES) {
        int d = g_edst[e];
        int p = atomicAdd(&g_head[d], 1);
        g_ssrc[g_off[d] + p] = g_esrc[e];
    }
}

// build transposed concatenated weights: g_wcat[k*128+j] = k<128 ? Wl[j][k] : Wr[j][k-128]
__global__ void prep_w_kernel(const float* __restrict__ Wl,
                              const float* __restrict__ Wr) {
    int idx = blockIdx.x * blockDim.x + threadIdx.x;   // < 32768
    int k = idx >> 7, j = idx & 127;
    g_wcat[idx] = (k < 128) ? Wl[j * 128 + k] : Wr[j * 128 + (k - 128)];
}

// ---------------- mean aggregation: one warp per node ------------------------
__global__ void agg_kernel(const float* __restrict__ xin) {
    int warp = threadIdx.x >> 5, lane = threadIdx.x & 31;
    int node = blockIdx.x * 8 + warp;                  // grid = N/8 exactly
    int beg = g_off[node], end = g_off[node + 1];
    float4 a = make_float4(0.f, 0.f, 0.f, 0.f);
    for (int e = beg; e < end; e++) {
        int s = g_ssrc[e];
        float4 t = *reinterpret_cast<const float4*>(xin + (size_t)s * D + lane * 4);
        a.x += t.x; a.y += t.y; a.z += t.z; a.w += t.w;
    }
    float inv = 1.0f / fmaxf((float)(end - beg), 1.0f);
    a.x *= inv; a.y *= inv; a.z *= inv; a.w *= inv;
    *reinterpret_cast<float4*>(g_agg + (size_t)node * D + lane * 4) = a;
}

// ---------------- fused GEMM + bias + L2 normalize (+relu) -------------------
// out[n][j] = sum_k g_wcat[k][j] * V[n][k],  V = [agg | xin]  (256 wide)
// 128 threads: tx=tid&15 -> 8 features, ty=tid>>4 -> 8 nodes (n = i*8+ty)
#define VS_STRIDE 260
#define SMEM_FLOATS (32768 + 64 * VS_STRIDE + 128)
#define SMEM_BYTES  (SMEM_FLOATS * 4)

__device__ __forceinline__ void ffma2(unsigned long long& d,
                                      unsigned long long a,
                                      unsigned long long b) {
    asm("fma.rn.f32x2 %0, %1, %2, %0;" : "+l"(d) : "l"(a), "l"(b));
}

__global__ __launch_bounds__(128, 1)
void gemm_kernel(const float* __restrict__ xin, const float* __restrict__ bias,
                 float* __restrict__ out, int relu, int nTiles) {
    extern __shared__ float sm[];
    float* Ws  = sm;                      // 256 x 128
    float* Vs  = sm + 32768;              // 64 x VS_STRIDE
    float* bls = Vs + 64 * VS_STRIDE;     // 128

    int tid = threadIdx.x;
    int tx = tid & 15, ty = tid >> 4;

    {   // weights + bias to smem (once; reused across all tiles)
        const float4* wsrc = reinterpret_cast<const float4*>(g_wcat);
        float4* wdst = reinterpret_cast<float4*>(Ws);
        for (int i = tid; i < 8192; i += 128) wdst[i] = wsrc[i];
        bls[tid] = bias[tid];
    }
    __syncthreads();

    for (int tile = blockIdx.x; tile < nTiles; tile += gridDim.x) {
        int n0 = tile * 64;

        // stage V tile: cols [0,128)=agg, [128,256)=xin
        for (int i = tid; i < 2048; i += 128) {
            int r = i >> 5, c4 = i & 31;
            int n = n0 + r;
            float4 va = make_float4(0.f, 0.f, 0.f, 0.f);
            float4 vx = va;
            if (n < N_NODES) {
                va = reinterpret_cast<const float4*>(g_agg + (size_t)n * D)[c4];
                vx = reinterpret_cast<const float4*>(xin   + (size_t)n * D)[c4];
            }
            *reinterpret_cast<float4*>(&Vs[r * VS_STRIDE + c4 * 4])       = va;
            *reinterpret_cast<float4*>(&Vs[r * VS_STRIDE + 128 + c4 * 4]) = vx;
        }
        __syncthreads();

        unsigned long long acc[8][4];
        #pragma unroll
        for (int i = 0; i < 8; i++)
            #pragma unroll
            for (int p = 0; p < 4; p++) acc[i][p] = 0ull;

        #pragma unroll 4
        for (int k = 0; k < 256; k++) {
            const ulonglong2* wp =
                reinterpret_cast<const ulonglong2*>(&Ws[k * 128 + tx * 8]);
            ulonglong2 wA = wp[0];   // feature pairs (0,1)(2,3)
            ulonglong2 wB = wp[1];   // feature pairs (4,5)(6,7)
            #pragma unroll
            for (int i = 0; i < 8; i++) {
                float v = Vs[(i * 8 + ty) * VS_STRIDE + k];
                unsigned long long vv;
                unsigned int vb = __float_as_uint(v);
                asm("mov.b64 %0, {%1, %1};" : "=l"(vv) : "r"(vb));
                ffma2(acc[i][0], wA.x, vv);
                ffma2(acc[i][1], wA.y, vv);
                ffma2(acc[i][2], wB.x, vv);
                ffma2(acc[i][3], wB.y, vv);
            }
        }

        // epilogue: bias, row L2-norm (16-lane butterfly), optional relu, store
        #pragma unroll
        for (int i = 0; i < 8; i++) {
            int n = n0 + i * 8 + ty;
            float o[8];
            #pragma unroll
            for (int p = 0; p < 4; p++) {
                unsigned int lo, hi;
                asm("mov.b64 {%0, %1}, %2;" : "=r"(lo), "=r"(hi) : "l"(acc[i][p]));
                o[2 * p]     = __uint_as_float(lo) + bls[tx * 8 + 2 * p];
                o[2 * p + 1] = __uint_as_float(hi) + bls[tx * 8 + 2 * p + 1];
            }
            float ss = 0.f;
            #pragma unroll
            for (int q = 0; q < 8; q++) ss += o[q] * o[q];
            #pragma unroll
            for (int m = 1; m < 16; m <<= 1)
                ss += __shfl_xor_sync(0xffffffffu, ss, m, 16);
            float scale = 1.0f / fmaxf(sqrtf(ss), 1e-12f);
            #pragma unroll
            for (int q = 0; q < 8; q++) {
                float z = o[q] * scale;
                o[q] = relu ? fmaxf(z, 0.f) : z;
            }
            if (n < N_NODES) {
                float4* op = reinterpret_cast<float4*>(out + (size_t)n * D + tx * 8);
                op[0] = make_float4(o[0], o[1], o[2], o[3]);
                op[1] = make_float4(o[4], o[5], o[6], o[7]);
            }
        }
        __syncthreads();
    }
}

// ---------------- launch ------------------------------------------------------
extern "C" void kernel_launch(void* const* d_in, const int* in_sizes, int n_in,
                              void* d_out, int out_size) {
    const float* x   = (const float*)d_in[0];
    const int*   ei  = (const int*)d_in[1];     // int32 view; dtype sniffed on device
    const float* Wl1 = (const float*)d_in[2];
    const float* bl1 = (const float*)d_in[3];
    const float* Wr1 = (const float*)d_in[4];
    const float* Wl2 = (const float*)d_in[5];
    const float* bl2 = (const float*)d_in[6];
    const float* Wr2 = (const float*)d_in[7];
    float* out = (float*)d_out;

    cudaFuncSetAttribute(gemm_kernel,
                         cudaFuncAttributeMaxDynamicSharedMemorySize, SMEM_BYTES);

    void* h1p = nullptr;
    cudaGetSymbolAddress(&h1p, g_h1);
    float* h1 = (float*)h1p;

    const int nTiles = (N_NODES + 63) / 64;
    const int GEMM_GRID = 152;   // ~1 resident block per SM (smem-limited)

    // edge dtype sniff + unpack, then bucketing (shared by both layers)
    detect_kernel<<<1, 32>>>(ei);
    convert_kernel<<<(2 * N_EDGES + 255) / 256, 256>>>(ei);
    zero_counts_kernel<<<(N_NODES + 255) / 256, 256>>>();
    count_kernel<<<(N_EDGES + 255) / 256, 256>>>();
    scan_kernel<<<1, 1024>>>();
    fill_kernel<<<(N_EDGES + 255) / 256, 256>>>();

    // layer 1
    prep_w_kernel<<<128, 256>>>(Wl1, Wr1);
    agg_kernel<<<N_NODES / 8, 256>>>(x);
    gemm_kernel<<<GEMM_GRID, 128, SMEM_BYTES>>>(x, bl1, h1, 1, nTiles);

    // layer 2
    prep_w_kernel<<<128, 256>>>(Wl2, Wr2);
    agg_kernel<<<N_NODES / 8, 256>>>(h1);
    gemm_kernel<<<GEMM_GRID, 128, SMEM_BYTES>>>(h1, bl2, out, 0, nTiles);
}

// round 17
// speedup vs baseline: 1.0363x; 1.0363x over previous
#include <cuda_runtime.h>
#include <cstdint>

#define N_NODES 100000
#define N_EDGES 640000
#define D 128

// ---------------- scratch (device globals: no runtime allocation allowed) ---
static __device__ int   g_is64;
static __device__ int   g_edst[N_EDGES];
static __device__ int   g_cnt[N_NODES];
static __device__ int   g_head[N_NODES];
static __device__ int   g_off[N_NODES + 1];
static __device__ int   g_ssrc[N_EDGES];
static __device__ float g_agg[(size_t)N_NODES * D];   // 51.2 MB
static __device__ float g_h1[(size_t)N_NODES * D];    // 51.2 MB
static __device__ float g_wcat[256 * 128];            // [Wl;Wr] transposed: [k][j]

// ---------------- edge dtype detection ---------------------------------------
// JAX without x64 downcasts int64->int32. If the buffer is int64 (LE, values
// < 2^31) every odd 32-bit word of the first 256 elements is 0.
__global__ void detect_kernel(const int* __restrict__ raw) {
    if (threadIdx.x == 0) {
        int nz = 0;
        #pragma unroll 8
        for (int i = 0; i < 256; i++) nz |= raw[2 * i + 1];
        g_is64 = (nz == 0) ? 1 : 0;
    }
}

__global__ void zero_counts_kernel() {
    int i = blockIdx.x * blockDim.x + threadIdx.x;
    if (i < N_NODES) { g_cnt[i] = 0; g_head[i] = 0; }
}

// convert dst half + histogram in one pass
__global__ void convert_count_kernel(const int* __restrict__ raw) {
    int e = blockIdx.x * blockDim.x + threadIdx.x;
    if (e >= N_EDGES) return;
    int v = g_is64 ? raw[2 * (N_EDGES + e)] : raw[N_EDGES + e];
    v = min(max(v, 0), N_NODES - 1);
    g_edst[e] = v;
    atomicAdd(&g_cnt[v], 1);
}

// single-block exclusive scan over g_cnt -> g_off (shfl-based, 3 BARs/iter)
__global__ void scan_kernel() {
    __shared__ int wsum[32];
    int t = threadIdx.x, lane = t & 31, w = t >> 5;
    int carry = 0;
    for (int base = 0; base < N_NODES; base += 1024) {
        int i = base + t;
        int v = (i < N_NODES) ? g_cnt[i] : 0;
        int s = v;
        #pragma unroll
        for (int o = 1; o < 32; o <<= 1) {
            int u = __shfl_up_sync(0xffffffffu, s, o);
            if (lane >= o) s += u;
        }
        if (lane == 31) wsum[w] = s;
        __syncthreads();
        if (w == 0) {
            int ws = wsum[lane];
            #pragma unroll
            for (int o = 1; o < 32; o <<= 1) {
                int u = __shfl_up_sync(0xffffffffu, ws, o);
                if (lane >= o) ws += u;
            }
            wsum[lane] = ws;
        }
        __syncthreads();
        int pre = (w > 0 ? wsum[w - 1] : 0) + (s - v) + carry;
        if (i < N_NODES) g_off[i] = pre;
        carry += wsum[31];
        __syncthreads();
    }
    if (t == 0) g_off[N_NODES] = carry;
}

__global__ void fill_kernel(const int* __restrict__ raw) {
    int e = blockIdx.x * blockDim.x + threadIdx.x;
    if (e >= N_EDGES) return;
    int s = g_is64 ? raw[2 * e] : raw[e];
    s = min(max(s, 0), N_NODES - 1);
    int d = g_edst[e];
    int p = atomicAdd(&g_head[d], 1);
    g_ssrc[g_off[d] + p] = s;
}

// g_wcat[k*128+j] = k<128 ? Wl[j][k] : Wr[j][k-128]
__global__ void prep_w_kernel(const float* __restrict__ Wl,
                              const float* __restrict__ Wr) {
    int idx = blockIdx.x * blockDim.x + threadIdx.x;   // < 32768
    int k = idx >> 7, j = idx & 127;
    g_wcat[idx] = (k < 128) ? Wl[j * 128 + k] : Wr[j * 128 + (k - 128)];
}

// ---------------- mean aggregation: one warp per node ------------------------
__global__ void agg_kernel(const float* __restrict__ xin) {
    int warp = threadIdx.x >> 5, lane = threadIdx.x & 31;
    int node = blockIdx.x * 8 + warp;                  // grid = N/8 exactly
    int beg = g_off[node], end = g_off[node + 1];
    float4 a0 = make_float4(0.f, 0.f, 0.f, 0.f);
    float4 a1 = a0;
    int e = beg;
    for (; e + 1 < end; e += 2) {
        int s0 = g_ssrc[e], s1 = g_ssrc[e + 1];
        float4 t0 = *reinterpret_cast<const float4*>(xin + (size_t)s0 * D + lane * 4);
        float4 t1 = *reinterpret_cast<const float4*>(xin + (size_t)s1 * D + lane * 4);
        a0.x += t0.x; a0.y += t0.y; a0.z += t0.z; a0.w += t0.w;
        a1.x += t1.x; a1.y += t1.y; a1.z += t1.z; a1.w += t1.w;
    }
    if (e < end) {
        int s0 = g_ssrc[e];
        float4 t0 = *reinterpret_cast<const float4*>(xin + (size_t)s0 * D + lane * 4);
        a0.x += t0.x; a0.y += t0.y; a0.z += t0.z; a0.w += t0.w;
    }
    float inv = 1.0f / fmaxf((float)(end - beg), 1.0f);
    a0.x = (a0.x + a1.x) * inv; a0.y = (a0.y + a1.y) * inv;
    a0.z = (a0.z + a1.z) * inv; a0.w = (a0.w + a1.w) * inv;
    *reinterpret_cast<float4*>(g_agg + (size_t)node * D + lane * 4) = a0;
}

// ---------------- fused GEMM + bias + L2 normalize (+relu) -------------------
// out[n][j] = sum_k Wcat[k][j] * V[n][k],  V = [agg | xin] (256 wide)
// 256 threads, 64-node tile. tx=tid&15 -> 8 features, ty=(tid>>4)&15 -> nodes
// {ty, 16+ty, 32+ty, 48+ty}. Register-prefetch pipeline over tiles.
#define VS_STRIDE 260
#define SMEM_FLOATS (32768 + 64 * VS_STRIDE + 128)
#define SMEM_BYTES  (SMEM_FLOATS * 4)

__device__ __forceinline__ void ffma2(unsigned long long& d,
                                      unsigned long long a,
                                      unsigned long long b) {
    asm("fma.rn.f32x2 %0, %1, %2, %0;" : "+l"(d) : "l"(a), "l"(b));
}

__global__ __launch_bounds__(256, 1)
void gemm_kernel(const float* __restrict__ xin, const float* __restrict__ bias,
                 float* __restrict__ out, int relu, int nTiles) {
    extern __shared__ float sm[];
    float* Ws  = sm;                      // 256 x 128
    float* Vs  = sm + 32768;              // 64 x VS_STRIDE
    float* bls = Vs + 64 * VS_STRIDE;     // 128

    int tid = threadIdx.x;
    int tx = tid & 15, ty = (tid >> 4) & 15;

    {   // weights + bias to smem (once; reused across all tiles)
        const float4* wsrc = reinterpret_cast<const float4*>(g_wcat);
        float4* wdst = reinterpret_cast<float4*>(Ws);
        for (int i = tid; i < 8192; i += 256) wdst[i] = wsrc[i];
        if (tid < 128) bls[tid] = bias[tid];
    }

    float4 pf[16];
    auto load_pf = [&](int t) {
        #pragma unroll
        for (int s = 0; s < 16; s++) {
            int i = tid + s * 256;         // 0..4095
            int r = i >> 6, c = i & 63;    // 64 float4 per row: 32 agg | 32 xin
            int n = t * 64 + r;
            float4 v = make_float4(0.f, 0.f, 0.f, 0.f);
            if (t < nTiles && n < N_NODES) {
                v = (c < 32)
                  ? reinterpret_cast<const float4*>(g_agg + (size_t)n * D)[c]
                  : reinterpret_cast<const float4*>(xin   + (size_t)n * D)[c - 32];
            }
            pf[s] = v;
        }
    };
    auto store_pf = [&]() {
        #pragma unroll
        for (int s = 0; s < 16; s++) {
            int i = tid + s * 256;
            int r = i >> 6, c = i & 63;
            *reinterpret_cast<float4*>(&Vs[r * VS_STRIDE + c * 4]) = pf[s];
        }
    };

    int tile = blockIdx.x;
    load_pf(tile);
    __syncthreads();              // weights/bias ready
    store_pf();
    __syncthreads();              // Vs ready

    while (tile < nTiles) {
        int nxt = tile + gridDim.x;
        load_pf(nxt);             // LDGs fly during compute

        unsigned long long acc[4][4];
        #pragma unroll
        for (int i = 0; i < 4; i++)
            #pragma unroll
            for (int p = 0; p < 4; p++) acc[i][p] = 0ull;

        #pragma unroll 4
        for (int k = 0; k < 256; k++) {
            const ulonglong2* wp =
                reinterpret_cast<const ulonglong2*>(&Ws[k * 128 + tx * 8]);
            ulonglong2 wA = wp[0];
            ulonglong2 wB = wp[1];
            #pragma unroll
            for (int i = 0; i < 4; i++) {
                float v = Vs[(i * 16 + ty) * VS_STRIDE + k];
                unsigned long long vv;
                unsigned int vb = __float_as_uint(v);
                asm("mov.b64 %0, {%1, %1};" : "=l"(vv) : "r"(vb));
                ffma2(acc[i][0], wA.x, vv);
                ffma2(acc[i][1], wA.y, vv);
                ffma2(acc[i][2], wB.x, vv);
                ffma2(acc[i][3], wB.y, vv);
            }
        }

        // epilogue: bias, row L2-norm (16-lane butterfly over tx), relu, store
        #pragma unroll
        for (int i = 0; i < 4; i++) {
            int n = tile * 64 + i * 16 + ty;
            float o[8];
            #pragma unroll
            for (int p = 0; p < 4; p++) {
                unsigned int lo, hi;
                asm("mov.b64 {%0, %1}, %2;" : "=r"(lo), "=r"(hi) : "l"(acc[i][p]));
                o[2 * p]     = __uint_as_float(lo) + bls[tx * 8 + 2 * p];
                o[2 * p + 1] = __uint_as_float(hi) + bls[tx * 8 + 2 * p + 1];
            }
            float ss = 0.f;
            #pragma unroll
            for (int q = 0; q < 8; q++) ss += o[q] * o[q];
            #pragma unroll
            for (int m = 1; m < 16; m <<= 1)
                ss += __shfl_xor_sync(0xffffffffu, ss, m, 16);
            float scale = 1.0f / fmaxf(sqrtf(ss), 1e-12f);
            #pragma unroll
            for (int q = 0; q < 8; q++) {
                float z = o[q] * scale;
                o[q] = relu ? fmaxf(z, 0.f) : z;
            }
            if (n < N_NODES) {
                float4* op = reinterpret_cast<float4*>(out + (size_t)n * D + tx * 8);
                op[0] = make_float4(o[0], o[1], o[2], o[3]);
                op[1] = make_float4(o[4], o[5], o[6], o[7]);
            }
        }

        __syncthreads();          // everyone done reading Vs
        store_pf();
        __syncthreads();          // Vs(nxt) ready
        tile = nxt;
    }
}

// ---------------- launch ------------------------------------------------------
extern "C" void kernel_launch(void* const* d_in, const int* in_sizes, int n_in,
                              void* d_out, int out_size) {
    const float* x   = (const float*)d_in[0];
    const int*   ei  = (const int*)d_in[1];     // int32 view; dtype sniffed
    const float* Wl1 = (const float*)d_in[2];
    const float* bl1 = (const float*)d_in[3];
    const float* Wr1 = (const float*)d_in[4];
    const float* Wl2 = (const float*)d_in[5];
    const float* bl2 = (const float*)d_in[6];
    const float* Wr2 = (const float*)d_in[7];
    float* out = (float*)d_out;

    cudaFuncSetAttribute(gemm_kernel,
                         cudaFuncAttributeMaxDynamicSharedMemorySize, SMEM_BYTES);

    void* h1p = nullptr;
    cudaGetSymbolAddress(&h1p, g_h1);
    float* h1 = (float*)h1p;

    const int nTiles = (N_NODES + 63) / 64;
    const int GEMM_GRID = 152;

    // edge dtype sniff + bucketing (shared by both layers)
    detect_kernel<<<1, 32>>>(ei);
    zero_counts_kernel<<<(N_NODES + 255) / 256, 256>>>();
    convert_count_kernel<<<(N_EDGES + 255) / 256, 256>>>(ei);
    scan_kernel<<<1, 1024>>>();
    fill_kernel<<<(N_EDGES + 255) / 256, 256>>>(ei);

    // layer 1
    prep_w_kernel<<<128, 256>>>(Wl1, Wr1);
    agg_kernel<<<N_NODES / 8, 256>>>(x);
    gemm_kernel<<<GEMM_GRID, 256, SMEM_BYTES>>>(x, bl1, h1, 1, nTiles);

    // layer 2
    prep_w_kernel<<<128, 256>>>(Wl2, Wr2);
    agg_kernel<<<N_NODES / 8, 256>>>(h1);
    gemm_kernel<<<GEMM_GRID, 256, SMEM_BYTES>>>(h1, bl2, out, 0, nTiles);
}